// round 9
// baseline (speedup 1.0000x reference)
#include <cuda_runtime.h>

#define B_    256
#define V_    128000
#define P_    512
#define O_    128
#define NT    512
#define NWARP 16
#define QS    4
#define VQ    (V_/QS)      // 32000
#define CQ    (VQ/4)       // 8000 float4 per quarter
#define HB    2048
#define HMASK (HB-1)
#define NBIN  4096
#define CCAP  4096
#define SSCAP 1024
#define RRCAP 256
#define TAU   2.0f
#define FB_SCAP 2048
#define FB_RCAP 1024
#define NEG_INF (__int_as_float(0xff800000))
#define TINYF 1.1754943508222875e-38f
#define EPS_T 1e-5f

// output layout (floats): [sampled B][idx B*21][lp B*21][ranks B]
#define IDX_OFF 256
#define LP_OFF  5632
#define RK_OFF  11008

// ---------------- global scratch ----------------
__device__ float g_cval[B_][CCAP];
__device__ int   g_cidx[B_][CCAP];
__device__ int   g_nc[B_];
__device__ float g_expsum[B_][QS];
__device__ int   g_flag[B_];

// ---------------- helpers ----------------
__device__ __forceinline__ int binOf(float f) {
    unsigned u = __float_as_uint(f);
    u = (u & 0x80000000u) ? ~u : (u | 0x80000000u);
    return (int)(u >> 20);
}
__device__ __forceinline__ unsigned f2ord(float f) {
    unsigned u = __float_as_uint(f);
    return (u & 0x80000000u) ? ~u : (u | 0x80000000u);
}
__device__ __forceinline__ float ord2f(unsigned o) {
    unsigned u = (o & 0x80000000u) ? (o & 0x7fffffffu) : ~o;
    return __uint_as_float(u);
}

// JAX threefry2x32 partitionable: key=(0,42), counter=(0, idx), bits=x0^x1
__device__ __forceinline__ float gumbel_at(unsigned idx) {
    const unsigned ks0 = 0u, ks1 = 42u, ks2 = 0x1BD11BDAu ^ 42u;
    unsigned x0 = ks0;
    unsigned x1 = idx + ks1;
#define TF_QR(r) { x0 += x1; x1 = (x1 << (r)) | (x1 >> (32 - (r))); x1 ^= x0; }
    TF_QR(13) TF_QR(15) TF_QR(26) TF_QR(6)   x0 += ks1; x1 += ks2 + 1u;
    TF_QR(17) TF_QR(29) TF_QR(16) TF_QR(24)  x0 += ks2; x1 += ks0 + 2u;
    TF_QR(13) TF_QR(15) TF_QR(26) TF_QR(6)   x0 += ks0; x1 += ks1 + 3u;
    TF_QR(17) TF_QR(29) TF_QR(16) TF_QR(24)  x0 += ks1; x1 += ks2 + 4u;
    TF_QR(13) TF_QR(15) TF_QR(26) TF_QR(6)   x0 += ks2; x1 += ks0 + 5u;
#undef TF_QR
    unsigned bits = x0 ^ x1;
    float f = __uint_as_float((bits >> 9) | 0x3F800000u) - 1.0f;
    float u = fmaxf(f + TINYF, TINYF);
    return -logf(-logf(u));
}

__device__ __forceinline__ unsigned hhash(int v) {
    return (((unsigned)v * 2654435761u) >> 21) & HMASK;
}
__device__ __forceinline__ int hinsert(int* hkey, int v) {
    unsigned h = hhash(v);
    while (true) {
        int k = hkey[h];
        if (k == v) return (int)h;
        if (k == -1) {
            int old = atomicCAS(&hkey[h], -1, v);
            if (old == -1 || old == v) return (int)h;
        }
        h = (h + 1) & HMASK;
    }
}
__device__ __forceinline__ int hfind(const int* hkey, int v) {
    unsigned h = hhash(v);
    while (true) {
        int k = hkey[h];
        if (k == v) return (int)h;
        if (k == -1) return -1;
        h = (h + 1) & HMASK;
    }
}

// penalty adjustment, matching reference fp order (x <= lg always)
__device__ __forceinline__ float adjv(float lg, int aux, float rp, float fq, float pp) {
    int cnt = aux & 0xFFFF;
    bool outseen = cnt > 0;
    bool seen = outseen || (aux & 0x10000);
    float y = lg;
    if (seen) y = (lg > 0.0f) ? (lg / rp) : (lg * rp);
    y = y - fq * (float)cnt;
    y = y - (outseen ? pp : 0.0f);
    return y;
}

// block argmax (val desc, idx asc)
__device__ void blk_argmax(float v, int idx, float* redf, int* redi, int tid,
                           float* ov, int* oidx) {
#pragma unroll
    for (int off = 16; off; off >>= 1) {
        float v2 = __shfl_down_sync(0xffffffffu, v, off);
        int   i2 = __shfl_down_sync(0xffffffffu, idx, off);
        if (v2 > v || (v2 == v && i2 < idx)) { v = v2; idx = i2; }
    }
    if ((tid & 31) == 0) { redf[tid >> 5] = v; redi[tid >> 5] = idx; }
    __syncthreads();
    if (tid < 32) {
        v = (tid < NWARP) ? redf[tid] : NEG_INF;
        idx = (tid < NWARP) ? redi[tid] : 0x7fffffff;
#pragma unroll
        for (int off = 16; off; off >>= 1) {
            float v2 = __shfl_down_sync(0xffffffffu, v, off);
            int   i2 = __shfl_down_sync(0xffffffffu, idx, off);
            if (v2 > v || (v2 == v && i2 < idx)) { v = v2; idx = i2; }
        }
        if (tid == 0) { redf[0] = v; redi[0] = idx; }
    }
    __syncthreads();
    *ov = redf[0]; *oidx = redi[0];
    __syncthreads();
}

__device__ int blk_isum(int v, int* redi, int tid) {
#pragma unroll
    for (int off = 16; off; off >>= 1) v += __shfl_down_sync(0xffffffffu, v, off);
    if ((tid & 31) == 0) redi[tid >> 5] = v;
    __syncthreads();
    if (tid < 32) {
        v = (tid < NWARP) ? redi[tid] : 0;
#pragma unroll
        for (int off = 16; off; off >>= 1) v += __shfl_down_sync(0xffffffffu, v, off);
        if (tid == 0) redi[0] = v;
    }
    __syncthreads();
    int r = redi[0];
    __syncthreads();
    return r;
}

// shared-hist top-tail cutoff: largest bin T with count(bins >= T) >= need
__device__ int cutoff_sh(const int* hist, int need, int* suf, int* selp, int* outp, int tid) {
    int part = 0;
    int b0 = tid * 8;
#pragma unroll
    for (int b = 0; b < 8; b++) part += hist[b0 + b];
    suf[tid] = part;
    __syncthreads();
    for (int off = 1; off < NT; off <<= 1) {
        int v = (tid + off < NT) ? suf[tid + off] : 0;
        __syncthreads();
        suf[tid] += v;
        __syncthreads();
    }
    if (suf[tid] >= need && (tid == NT - 1 || suf[tid + 1] < need)) *selp = tid;
    __syncthreads();
    if (tid == 0) {
        int c = *selp;
        int acc = (c < NT - 1) ? suf[c + 1] : 0;
        int T = c * 8;
        for (int b = c * 8 + 7; b >= c * 8; b--) {
            acc += hist[b];
            if (acc >= need) { T = b; break; }
        }
        *outp = T;
    }
    __syncthreads();
    int T = *outp;
    __syncthreads();
    return T;
}

// ---------------- K0: zero counters/flags ----------------
__global__ void k0_zero() {
    int i = threadIdx.x;
    if (i < B_) { g_nc[i] = 0; g_flag[i] = 0; }
}

// ---------------- K1: single streaming pass ----------------
__global__ __launch_bounds__(NT) void k1_stream(const float* __restrict__ logits) {
    __shared__ float redf[NWARP];
    const int tid = threadIdx.x, lane = tid & 31;
    const int r = blockIdx.x / QS, q = blockIdx.x % QS;
    const float4* q4 = (const float4*)(logits + (size_t)r * V_ + (size_t)q * VQ);
    const int base = q * VQ;
    float s0 = 0.f, s1 = 0.f, s2 = 0.f, s3 = 0.f;

    for (int i0 = tid; i0 < CQ; i0 += 2 * NT) {
        const int i1 = i0 + NT;
        const bool h2 = (i1 < CQ);   // uniform within warp (boundary at multiple of 32)
        float4 A = q4[i0];
        float4 Bv;
        if (h2) Bv = q4[i1];

        s0 += __expf(A.x); s1 += __expf(A.y); s2 += __expf(A.z); s3 += __expf(A.w);
        {
            int v0 = base + 4 * i0;
#pragma unroll
            for (int j = 0; j < 4; j++) {
                float lg = (&A.x)[j];
                bool pred = (lg >= TAU);
                unsigned msk = __ballot_sync(0xffffffffu, pred);
                if (msk) {
                    int ldr = __ffs(msk) - 1, cnt = __popc(msk), bp = 0;
                    if (lane == ldr) bp = atomicAdd(&g_nc[r], cnt);
                    bp = __shfl_sync(0xffffffffu, bp, ldr);
                    if (pred) {
                        int off = bp + __popc(msk & ((1u << lane) - 1u));
                        if (off < CCAP) { g_cval[r][off] = lg; g_cidx[r][off] = v0 + j; }
                    }
                }
            }
        }
        if (h2) {
            s0 += __expf(Bv.x); s1 += __expf(Bv.y); s2 += __expf(Bv.z); s3 += __expf(Bv.w);
            int v0 = base + 4 * i1;
#pragma unroll
            for (int j = 0; j < 4; j++) {
                float lg = (&Bv.x)[j];
                bool pred = (lg >= TAU);
                unsigned msk = __ballot_sync(0xffffffffu, pred);
                if (msk) {
                    int ldr = __ffs(msk) - 1, cnt = __popc(msk), bp = 0;
                    if (lane == ldr) bp = atomicAdd(&g_nc[r], cnt);
                    bp = __shfl_sync(0xffffffffu, bp, ldr);
                    if (pred) {
                        int off = bp + __popc(msk & ((1u << lane) - 1u));
                        if (off < CCAP) { g_cval[r][off] = lg; g_cidx[r][off] = v0 + j; }
                    }
                }
            }
        }
    }

    float sv = (s0 + s1) + (s2 + s3);
#pragma unroll
    for (int off = 16; off; off >>= 1) sv += __shfl_down_sync(0xffffffffu, sv, off);
    if ((tid & 31) == 0) redf[tid >> 5] = sv;
    __syncthreads();
    if (tid < 32) {
        float v = (tid < NWARP) ? redf[tid] : 0.f;
#pragma unroll
        for (int off = 16; off; off >>= 1) v += __shfl_down_sync(0xffffffffu, v, off);
        if (tid == 0) g_expsum[r][q] = v;
    }
}

// ---------------- K2: per-row selection on candidates ----------------
struct M2 {
    int   suf[NT];
    float redf[NWARP];
    int   redi[NWARP];
    int   selp, outp, cnt, bad;
    float lse, thresh, t_thr, lp_samp;
    int   keepN, sampled;
};
#define C2_HKEY 0
#define C2_HAUX 8192
#define C2_CVAL 16384
#define C2_CIDX 32768
#define C2_XVAL 49152
#define C2_HIST 65536
#define C2_TMPV 81920
#define C2_TMPI 86016
#define C2_SSV  90112
#define C2_SSI  94208
#define C2_RSV  98304
#define C2_RSI  99328
#define C2_MISC 100352
#define K2_SMEM (C2_MISC + 2560)

__global__ __launch_bounds__(NT) void k2_select(
    const float* __restrict__ logits,
    const float* __restrict__ temperature, const float* __restrict__ top_p,
    const float* __restrict__ freqp, const float* __restrict__ presp,
    const float* __restrict__ repp, const int* __restrict__ topk,
    const int* __restrict__ ptoks, const int* __restrict__ otoks,
    float* __restrict__ out)
{
    extern __shared__ unsigned char sm[];
    int*   hkey = (int*)(sm + C2_HKEY);
    int*   haux = (int*)(sm + C2_HAUX);
    float* cval = (float*)(sm + C2_CVAL);
    int*   cidx = (int*)(sm + C2_CIDX);
    float* xval = (float*)(sm + C2_XVAL);
    int*   hist = (int*)(sm + C2_HIST);
    float* tmpv = (float*)(sm + C2_TMPV);
    int*   tmpi = (int*)(sm + C2_TMPI);
    float* ssv  = (float*)(sm + C2_SSV);
    int*   ssi  = (int*)(sm + C2_SSI);
    float* rsv  = (float*)(sm + C2_RSV);
    int*   rsi  = (int*)(sm + C2_RSI);
    M2*    ms   = (M2*)(sm + C2_MISC);

    const int tid = threadIdx.x, r = blockIdx.x;
    int k = topk[r];
    if (k < 1) k = 1; if (k > V_) k = V_;
    const int ncand = g_nc[r];
    if (ncand > CCAP || ncand < k + 640) { if (tid == 0) g_flag[r] = 1; return; }

    const float tr = temperature[r], tpv = top_p[r];
    const float fq = freqp[r], pp = presp[r], rp = repp[r];
    const float tsafe = (tr < EPS_T) ? 1.0f : tr;

    for (int i = tid; i < HB; i += NT) { hkey[i] = -1; haux[i] = 0; }
    for (int i = tid; i < NBIN; i += NT) hist[i] = 0;
    if (tid == 0) {
        ms->cnt = 0;
        float e = (g_expsum[r][0] + g_expsum[r][1]) + (g_expsum[r][2] + g_expsum[r][3]);
        ms->lse = logf(e);
    }
    __syncthreads();
    for (int t = tid; t < O_; t += NT) atomicAdd(&haux[hinsert(hkey, otoks[r * O_ + t])], 1);
    for (int t = tid; t < P_; t += NT) atomicOr(&haux[hinsert(hkey, ptoks[r * P_ + t])], 1 << 16);
    __syncthreads();

    // load candidates, compute adjusted x, histogram x
    for (int i = tid; i < ncand; i += NT) {
        float lg = g_cval[r][i]; int v = g_cidx[r][i];
        cval[i] = lg; cidx[i] = v;
        int slot = hfind(hkey, v);
        float x = (slot >= 0) ? adjv(lg, haux[slot], rp, fq, pp) : lg;
        xval[i] = x;
        atomicAdd(&hist[binOf(x)], 1);
    }
    __syncthreads();
    int Ts = cutoff_sh(hist, k, ms->suf, &ms->selp, &ms->outp, tid);

    // collect x survivors
    for (int i = tid; i < ncand; i += NT) {
        if (binOf(xval[i]) >= Ts) {
            int p = atomicAdd(&ms->cnt, 1);
            if (p < SSCAP) { tmpv[p] = xval[i]; tmpi[p] = cidx[i]; }
        }
    }
    __syncthreads();
    int ss = ms->cnt;
    if (ss > SSCAP) { if (tid == 0) g_flag[r] = 1; return; }
    // sort x survivors (val desc, idx asc)
    for (int i = tid; i < ss; i += NT) {
        float v = tmpv[i]; int id = tmpi[i]; int rk = 0;
        for (int j = 0; j < ss; j++) {
            float w = tmpv[j];
            rk += (w > v) || (w == v && tmpi[j] < id);
        }
        ssv[rk] = v; ssi[rk] = id;
    }
    __syncthreads();

    // raw hist (reuse)
    for (int i = tid; i < NBIN; i += NT) hist[i] = 0;
    if (tid == 0) ms->cnt = 0;
    __syncthreads();
    for (int i = tid; i < ncand; i += NT) atomicAdd(&hist[binOf(cval[i])], 1);
    __syncthreads();
    int Tr = cutoff_sh(hist, 20, ms->suf, &ms->selp, &ms->outp, tid);
    for (int i = tid; i < ncand; i += NT) {
        if (binOf(cval[i]) >= Tr) {
            int p = atomicAdd(&ms->cnt, 1);
            if (p < RRCAP) { tmpv[p] = cval[i]; tmpi[p] = cidx[i]; }
        }
    }
    __syncthreads();
    int rr = ms->cnt;
    if (rr > RRCAP) { if (tid == 0) g_flag[r] = 1; return; }
    for (int i = tid; i < rr; i += NT) {
        float v = tmpv[i]; int id = tmpi[i]; int rk = 0;
        for (int j = 0; j < rr; j++) {
            float w = tmpv[j];
            rk += (w > v) || (w == v && tmpi[j] < id);
        }
        rsv[rk] = v; rsi[rk] = id;
    }
    __syncthreads();

    // top-k / top-p threshold
    if (tid == 0) {
        int kk = (k <= ss) ? k : ss;   // ss >= k guaranteed by cutoff
        float kth_s = ssv[kk - 1] / tsafe;
        int keepN = kk;
        while (keepN < ss && (ssv[keepN] / tsafe) >= kth_s) keepN++;
        float s0 = ssv[0] / tsafe;
        float S = 0.0f;
        for (int i = 0; i < keepN; i++) S += expf(ssv[i] / tsafe - s0);
        float cum = 0.0f; int j = 0;
        for (int i = 0; i < keepN; i++) {
            float p = expf(ssv[i] / tsafe - s0) / S;
            if (cum < tpv) j++;
            cum += p;
        }
        if (cum < tpv) j += (V_ - keepN);   // zero-prob tail all keeps
        int nkeep = (j < 1) ? 1 : j;
        float pth = (nkeep <= keepN) ? (ssv[nkeep - 1] / tsafe) : NEG_INF;
        ms->thresh = fmaxf(kth_s, pth);
        ms->keepN = keepN;
    }
    __syncthreads();
    const float thresh = ms->thresh;
    const int keepN = ms->keepN;
    const float lse = ms->lse;

    // gumbel argmax over kept candidates
    float bv = NEG_INF; int bidx = 0x7fffffff;
    for (int i = tid; i < keepN; i += NT) {
        float s = ssv[i] / tsafe;
        if (s >= thresh) {
            float g = gumbel_at((unsigned)(r * V_) + (unsigned)ssi[i]);
            float val = s + g;
            if (val > bv || (val == bv && ssi[i] < bidx)) { bv = val; bidx = ssi[i]; }
        }
    }
    float rv; int ri;
    blk_argmax(bv, bidx, ms->redf, ms->redi, tid, &rv, &ri);
    if (tid == 0) {
        int sampled = (tr < EPS_T) ? ssi[0] : ri;   // greedy = first-index argmax of x
        ms->sampled = sampled;
        float lgs = logits[(size_t)r * V_ + sampled];
        float c = lgs - lse;
        ms->lp_samp = c;
        unsigned lo = 0u, hi = f2ord(lgs);
        while (lo < hi) {
            unsigned mid = lo + ((hi - lo) >> 1);
            float y = ord2f(mid);
            if ((y - lse) >= c) hi = mid; else lo = mid + 1;
        }
        float t = ord2f(hi);
        ms->t_thr = t;
        ms->bad = (t < TAU) ? 1 : 0;
        if (ms->bad) g_flag[r] = 1;
    }
    __syncthreads();
    if (ms->bad) return;
    const float t_thr = ms->t_thr;

    // rank: count candidates with lg >= t_thr (complete since t_thr >= TAU)
    int cnt = 0;
    for (int i = tid; i < ncand; i += NT) cnt += (cval[i] >= t_thr) ? 1 : 0;
    int total = blk_isum(cnt, ms->redi, tid);

    // outputs
    if (tid < 20) {
        out[IDX_OFF + r * 21 + tid] = (float)rsi[tid];
        out[LP_OFF  + r * 21 + tid] = rsv[tid] - lse;
    }
    if (tid == 0) {
        out[r] = (float)ms->sampled;
        out[IDX_OFF + r * 21 + 20] = (float)ms->sampled;
        out[LP_OFF  + r * 21 + 20] = ms->lp_samp;
        out[RK_OFF + r] = (float)total;
    }
}

// ---------------- K3: exact fallback (round-5 logic), runs only when flagged ----------------
struct FbMisc {
    int   suf[NT];
    float redf[NWARP];
    float redf2[NWARP];
    int   redi[NWARP];
    float m, logS, thresh, lp_samp, t_thr;
    int   Ts, Tr, nsCnt, nrCnt, selp, outp, keepN, sampled, rank_ok;
};
#define FB_HKEY  0
#define FB_HAUX  8192
#define FB_HISTR 16384
#define FB_HISTS 32768
#define FB_SVAL  16384
#define FB_SIDX  24576
#define FB_RVAL  32768
#define FB_RIDX  36864
#define FB_SSV   0
#define FB_SSI   8192
#define FB_RSV   40960
#define FB_RSI   45056
#define FB_MISC  49152
#define FB_SMEM  (FB_MISC + 2816)

__global__ __launch_bounds__(NT) void k3_fallback(
    const float* __restrict__ logits,
    const float* __restrict__ temperature, const float* __restrict__ top_p,
    const float* __restrict__ freqp, const float* __restrict__ presp,
    const float* __restrict__ repp, const int* __restrict__ topk,
    const int* __restrict__ ptoks, const int* __restrict__ otoks,
    float* __restrict__ out)
{
    const int r = blockIdx.x;
    if (g_flag[r] == 0) return;

    extern __shared__ unsigned char sm[];
    int*    hkey  = (int*)(sm + FB_HKEY);
    int*    haux  = (int*)(sm + FB_HAUX);
    int*    histR = (int*)(sm + FB_HISTR);
    int*    histS = (int*)(sm + FB_HISTS);
    FbMisc* ms    = (FbMisc*)(sm + FB_MISC);

    const int tid = threadIdx.x;
    const float* row = logits + (size_t)r * V_;
    const float4* row4 = (const float4*)row;

    const float tr  = temperature[r];
    const float tpv = top_p[r];
    const float fq  = freqp[r];
    const float pp  = presp[r];
    const float rp  = repp[r];
    int k = topk[r];
    if (k < 1) k = 1; if (k > V_) k = V_;
    const float tsafe = (tr < EPS_T) ? 1.0f : tr;

    for (int i = tid; i < NBIN; i += NT) histR[i] = 0;
    for (int i = tid; i < HB; i += NT) { hkey[i] = -1; haux[i] = 0; }
    if (tid == 0) { ms->nsCnt = 0; ms->nrCnt = 0; }
    __syncthreads();

    for (int t = tid; t < O_; t += NT) atomicAdd(&haux[hinsert(hkey, otoks[r * O_ + t])], 1);
    for (int t = tid; t < P_; t += NT) atomicOr(&haux[hinsert(hkey, ptoks[r * P_ + t])], 1 << 16);
    __syncthreads();

    // pass 1: raw histogram + online logsumexp
    float ml0 = NEG_INF, ml1 = NEG_INF, ml2 = NEG_INF, ml3 = NEG_INF;
    float sl0 = 0.f, sl1 = 0.f, sl2 = 0.f, sl3 = 0.f;
    for (int i = tid; i < V_ / 4; i += NT) {
        float4 L = row4[i];
        if (L.x > ml0) { sl0 = sl0 * __expf(ml0 - L.x) + 1.0f; ml0 = L.x; } else sl0 += __expf(L.x - ml0);
        if (L.y > ml1) { sl1 = sl1 * __expf(ml1 - L.y) + 1.0f; ml1 = L.y; } else sl1 += __expf(L.y - ml1);
        if (L.z > ml2) { sl2 = sl2 * __expf(ml2 - L.z) + 1.0f; ml2 = L.z; } else sl2 += __expf(L.z - ml2);
        if (L.w > ml3) { sl3 = sl3 * __expf(ml3 - L.w) + 1.0f; ml3 = L.w; } else sl3 += __expf(L.w - ml3);
        atomicAdd(&histR[binOf(L.x)], 1);
        atomicAdd(&histR[binOf(L.y)], 1);
        atomicAdd(&histR[binOf(L.z)], 1);
        atomicAdd(&histR[binOf(L.w)], 1);
    }
    float mloc = fmaxf(fmaxf(ml0, ml1), fmaxf(ml2, ml3));
    float sloc = 0.0f;
    if (ml0 > NEG_INF) sloc += sl0 * __expf(ml0 - mloc);
    if (ml1 > NEG_INF) sloc += sl1 * __expf(ml1 - mloc);
    if (ml2 > NEG_INF) sloc += sl2 * __expf(ml2 - mloc);
    if (ml3 > NEG_INF) sloc += sl3 * __expf(ml3 - mloc);
    {
#pragma unroll
        for (int off = 16; off; off >>= 1) {
            float m2 = __shfl_down_sync(0xffffffffu, mloc, off);
            float s2 = __shfl_down_sync(0xffffffffu, sloc, off);
            float nm = fmaxf(mloc, m2);
            sloc = sloc * __expf(mloc - nm) + s2 * __expf(m2 - nm);
            mloc = nm;
        }
        if ((tid & 31) == 0) { ms->redf[tid >> 5] = mloc; ms->redf2[tid >> 5] = sloc; }
        __syncthreads();
        if (tid < 32) {
            float mm = (tid < NWARP) ? ms->redf[tid] : NEG_INF;
            float ssx = (tid < NWARP) ? ms->redf2[tid] : 0.0f;
#pragma unroll
            for (int off = 16; off; off >>= 1) {
                float m2 = __shfl_down_sync(0xffffffffu, mm, off);
                float s2 = __shfl_down_sync(0xffffffffu, ssx, off);
                float nm = fmaxf(mm, m2);
                ssx = ssx * __expf(mm - nm) + s2 * __expf(m2 - nm);
                mm = nm;
            }
            if (tid == 0) { ms->m = mm; ms->logS = logf(ssx); }
        }
        __syncthreads();
    }
    const float m = ms->m, logS = ms->logS;

    // histS = histR + corrections
    for (int i = tid; i < NBIN; i += NT) histS[i] = histR[i];
    __syncthreads();
    for (int s = tid; s < HB; s += NT) {
        int v = hkey[s];
        if (v >= 0) {
            float lg = row[v];
            float x = adjv(lg, haux[s], rp, fq, pp);
            int b1 = binOf(lg), b2 = binOf(x);
            if (b1 != b2) { atomicSub(&histS[b1], 1); atomicAdd(&histS[b2], 1); }
        }
    }
    __syncthreads();

    int Ts = cutoff_sh(histS, k, ms->suf, &ms->selp, &ms->outp, tid);
    int Tr = cutoff_sh(histR, 20, ms->suf, &ms->selp, &ms->outp, tid);
    if (tid == 0) { ms->Ts = Ts; ms->Tr = Tr; }
    const int Tmin = (Ts < Tr) ? Ts : Tr;
    __syncthreads();

    float* s_val = (float*)(sm + FB_SVAL);
    int*   s_idx = (int*)(sm + FB_SIDX);
    float* r_val = (float*)(sm + FB_RVAL);
    int*   r_idx = (int*)(sm + FB_RIDX);

    for (int i = tid; i < V_ / 4; i += NT) {
        float4 L = row4[i];
        int v0 = 4 * i;
#pragma unroll
        for (int j = 0; j < 4; j++) {
            float lg = (&L.x)[j];
            int b = binOf(lg);
            if (b >= Tmin) {
                int v = v0 + j;
                if (b >= Tr) {
                    int p = atomicAdd(&ms->nrCnt, 1);
                    if (p < FB_RCAP) { r_val[p] = lg; r_idx[p] = v; }
                }
                if (b >= Ts) {
                    float x = lg;
                    int slot = hfind(hkey, v);
                    if (slot >= 0) x = adjv(lg, haux[slot], rp, fq, pp);
                    if (binOf(x) >= Ts) {
                        int ps = atomicAdd(&ms->nsCnt, 1);
                        if (ps < FB_SCAP) { s_val[ps] = x; s_idx[ps] = v; }
                    }
                }
            }
        }
    }
    __syncthreads();
    int ns = ms->nsCnt; if (ns > FB_SCAP) ns = FB_SCAP;
    int nr = ms->nrCnt; if (nr > FB_RCAP) nr = FB_RCAP;
    int nrFull = ms->nrCnt;
    __syncthreads();

    float* ssv2 = (float*)(sm + FB_SSV);
    int*   ssi2 = (int*)(sm + FB_SSI);
    float* rsv2 = (float*)(sm + FB_RSV);
    int*   rsi2 = (int*)(sm + FB_RSI);

    for (int i = tid; i < ns; i += NT) {
        float v = s_val[i]; int id = s_idx[i]; int rk = 0;
        for (int j = 0; j < ns; j++) {
            float w = s_val[j];
            rk += (w > v) || (w == v && s_idx[j] < id);
        }
        ssv2[rk] = v; ssi2[rk] = id;
    }
    for (int i = tid; i < nr; i += NT) {
        float v = r_val[i]; int id = r_idx[i]; int rk = 0;
        for (int j = 0; j < nr; j++) {
            float w = r_val[j];
            rk += (w > v) || (w == v && r_idx[j] < id);
        }
        rsv2[rk] = v; rsi2[rk] = id;
    }
    __syncthreads();

    if (tid == 0) {
        int kk = (k <= ns) ? k : ns;
        float kth_s = ssv2[kk - 1] / tsafe;
        int keepN = kk;
        while (keepN < ns && (ssv2[keepN] / tsafe) >= kth_s) keepN++;
        float s0 = ssv2[0] / tsafe;
        float S = 0.0f;
        for (int i = 0; i < keepN; i++) S += expf(ssv2[i] / tsafe - s0);
        float cum = 0.0f; int j = 0;
        for (int i = 0; i < keepN; i++) {
            float p = expf(ssv2[i] / tsafe - s0) / S;
            if (cum < tpv) j++;
            cum += p;
        }
        if (cum < tpv) j += (V_ - keepN);
        int nkeep = (j < 1) ? 1 : j;
        float pth = (nkeep <= keepN) ? (ssv2[nkeep - 1] / tsafe) : NEG_INF;
        ms->thresh = fmaxf(kth_s, pth);
        ms->keepN = keepN;
    }
    __syncthreads();
    const float thresh = ms->thresh;
    const int keepN = ms->keepN;

    {
        float bv = NEG_INF; int bidx = 0x7fffffff;
        for (int i = tid; i < keepN; i += NT) {
            float s = ssv2[i] / tsafe;
            if (s >= thresh) {
                float g = gumbel_at((unsigned)(r * V_) + (unsigned)ssi2[i]);
                float val = s + g;
                if (val > bv || (val == bv && ssi2[i] < bidx)) { bv = val; bidx = ssi2[i]; }
            }
        }
        float rv; int ri;
        blk_argmax(bv, bidx, ms->redf, ms->redi, tid, &rv, &ri);
        if (tid == 0) {
            int sampled = (tr < EPS_T) ? ssi2[0] : ri;
            ms->sampled = sampled;
            float lgs = row[sampled];
            float c = (lgs - m) - logS;
            ms->lp_samp = c;
            unsigned lo = 0u, hi = f2ord(lgs);
            while (lo < hi) {
                unsigned mid = lo + ((hi - lo) >> 1);
                float y = ord2f(mid);
                if (((y - m) - logS) >= c) hi = mid; else lo = mid + 1;
            }
            float t = ord2f(hi);
            ms->t_thr = t;
            ms->rank_ok = (binOf(t) >= ms->Tr) && (nrFull <= FB_RCAP);
        }
        __syncthreads();
    }
    const int sampled = ms->sampled;
    const float lp_samp = ms->lp_samp;
    const float t_thr = ms->t_thr;
    const int rank_ok = ms->rank_ok;

    if (tid < 20) {
        out[IDX_OFF + r * 21 + tid] = (float)rsi2[tid];
        out[LP_OFF  + r * 21 + tid] = (rsv2[tid] - m) - logS;
    }
    if (tid == 0) {
        out[r] = (float)sampled;
        out[IDX_OFF + r * 21 + 20] = (float)sampled;
        out[LP_OFF  + r * 21 + 20] = lp_samp;
    }

    int cnt = 0;
    if (rank_ok) {
        for (int i = tid; i < nr; i += NT) cnt += (rsv2[i] >= t_thr) ? 1 : 0;
    } else {
        for (int i = tid; i < V_ / 4; i += NT) {
            float4 L = row4[i];
            cnt += (L.x >= t_thr) + (L.y >= t_thr) + (L.z >= t_thr) + (L.w >= t_thr);
        }
    }
    int total = blk_isum(cnt, ms->redi, tid);
    if (tid == 0) out[RK_OFF + r] = (float)total;
}

// ---------------- launch ----------------
extern "C" void kernel_launch(void* const* d_in, const int* in_sizes, int n_in,
                              void* d_out, int out_size) {
    const float* logits = (const float*)d_in[0];
    const float* temperature = (const float*)d_in[1];
    const float* topp = (const float*)d_in[2];
    const float* freqp = (const float*)d_in[3];
    const float* presp = (const float*)d_in[4];
    const float* repp = (const float*)d_in[5];
    const int* topk = (const int*)d_in[6];
    const int* ptoks = (const int*)d_in[7];
    const int* otoks = (const int*)d_in[8];
    float* out = (float*)d_out;

    cudaFuncSetAttribute(k2_select, cudaFuncAttributeMaxDynamicSharedMemorySize, K2_SMEM);
    cudaFuncSetAttribute(k3_fallback, cudaFuncAttributeMaxDynamicSharedMemorySize, FB_SMEM);

    k0_zero<<<1, NT>>>();
    k1_stream<<<B_ * QS, NT>>>(logits);
    k2_select<<<B_, NT, K2_SMEM>>>(logits, temperature, topp, freqp, presp, repp,
                                   topk, ptoks, otoks, out);
    k3_fallback<<<B_, NT, FB_SMEM>>>(logits, temperature, topp, freqp, presp, repp,
                                     topk, ptoks, otoks, out);
}

// round 10
// speedup vs baseline: 3.2162x; 3.2162x over previous
#include <cuda_runtime.h>

#define B_    256
#define V_    128000
#define P_    512
#define O_    128
#define NT    512
#define NWARP 16
#define QS    4
#define VQ    (V_/QS)      // 32000
#define CQ    (VQ/4)       // 8000 float4 per quarter
#define HB    2048
#define HMASK (HB-1)
#define NBIN  4096
#define CCAP  4096
#define SHCAP 2048
#define SSCAP 1024
#define RRCAP 256
#define TAU   2.0f
#define FB_SCAP 2048
#define FB_RCAP 1024
#define NEG_INF (__int_as_float(0xff800000))
#define TINYF 1.1754943508222875e-38f
#define EPS_T 1e-5f

// output layout (floats): [sampled B][idx B*21][lp B*21][ranks B]
#define IDX_OFF 256
#define LP_OFF  5632
#define RK_OFF  11008

// ---------------- global scratch ----------------
__device__ float g_cval[B_][CCAP];
__device__ int   g_cidx[B_][CCAP];
__device__ int   g_nc[B_];
__device__ float g_expsum[B_][QS];
__device__ int   g_flag[B_];

// ---------------- helpers ----------------
__device__ __forceinline__ int binOf(float f) {
    unsigned u = __float_as_uint(f);
    u = (u & 0x80000000u) ? ~u : (u | 0x80000000u);
    return (int)(u >> 20);
}
__device__ __forceinline__ unsigned f2ord(float f) {
    unsigned u = __float_as_uint(f);
    return (u & 0x80000000u) ? ~u : (u | 0x80000000u);
}
__device__ __forceinline__ float ord2f(unsigned o) {
    unsigned u = (o & 0x80000000u) ? (o & 0x7fffffffu) : ~o;
    return __uint_as_float(u);
}

// JAX threefry2x32 partitionable: key=(0,42), counter=(0, idx), bits=x0^x1
__device__ __forceinline__ float gumbel_at(unsigned idx) {
    const unsigned ks0 = 0u, ks1 = 42u, ks2 = 0x1BD11BDAu ^ 42u;
    unsigned x0 = ks0;
    unsigned x1 = idx + ks1;
#define TF_QR(r) { x0 += x1; x1 = (x1 << (r)) | (x1 >> (32 - (r))); x1 ^= x0; }
    TF_QR(13) TF_QR(15) TF_QR(26) TF_QR(6)   x0 += ks1; x1 += ks2 + 1u;
    TF_QR(17) TF_QR(29) TF_QR(16) TF_QR(24)  x0 += ks2; x1 += ks0 + 2u;
    TF_QR(13) TF_QR(15) TF_QR(26) TF_QR(6)   x0 += ks0; x1 += ks1 + 3u;
    TF_QR(17) TF_QR(29) TF_QR(16) TF_QR(24)  x0 += ks1; x1 += ks2 + 4u;
    TF_QR(13) TF_QR(15) TF_QR(26) TF_QR(6)   x0 += ks2; x1 += ks0 + 5u;
#undef TF_QR
    unsigned bits = x0 ^ x1;
    float f = __uint_as_float((bits >> 9) | 0x3F800000u) - 1.0f;
    float u = fmaxf(f + TINYF, TINYF);
    return -logf(-logf(u));
}

__device__ __forceinline__ unsigned hhash(int v) {
    return (((unsigned)v * 2654435761u) >> 21) & HMASK;
}
__device__ __forceinline__ int hinsert(int* hkey, int v) {
    unsigned h = hhash(v);
    while (true) {
        int k = hkey[h];
        if (k == v) return (int)h;
        if (k == -1) {
            int old = atomicCAS(&hkey[h], -1, v);
            if (old == -1 || old == v) return (int)h;
        }
        h = (h + 1) & HMASK;
    }
}
__device__ __forceinline__ int hfind(const int* hkey, int v) {
    unsigned h = hhash(v);
    while (true) {
        int k = hkey[h];
        if (k == v) return (int)h;
        if (k == -1) return -1;
        h = (h + 1) & HMASK;
    }
}

// penalty adjustment, matching reference fp order (x <= lg always)
__device__ __forceinline__ float adjv(float lg, int aux, float rp, float fq, float pp) {
    int cnt = aux & 0xFFFF;
    bool outseen = cnt > 0;
    bool seen = outseen || (aux & 0x10000);
    float y = lg;
    if (seen) y = (lg > 0.0f) ? (lg / rp) : (lg * rp);
    y = y - fq * (float)cnt;
    y = y - (outseen ? pp : 0.0f);
    return y;
}

// block argmax (val desc, idx asc)
__device__ void blk_argmax(float v, int idx, float* redf, int* redi, int tid,
                           float* ov, int* oidx) {
#pragma unroll
    for (int off = 16; off; off >>= 1) {
        float v2 = __shfl_down_sync(0xffffffffu, v, off);
        int   i2 = __shfl_down_sync(0xffffffffu, idx, off);
        if (v2 > v || (v2 == v && i2 < idx)) { v = v2; idx = i2; }
    }
    if ((tid & 31) == 0) { redf[tid >> 5] = v; redi[tid >> 5] = idx; }
    __syncthreads();
    if (tid < 32) {
        v = (tid < NWARP) ? redf[tid] : NEG_INF;
        idx = (tid < NWARP) ? redi[tid] : 0x7fffffff;
#pragma unroll
        for (int off = 16; off; off >>= 1) {
            float v2 = __shfl_down_sync(0xffffffffu, v, off);
            int   i2 = __shfl_down_sync(0xffffffffu, idx, off);
            if (v2 > v || (v2 == v && i2 < idx)) { v = v2; idx = i2; }
        }
        if (tid == 0) { redf[0] = v; redi[0] = idx; }
    }
    __syncthreads();
    *ov = redf[0]; *oidx = redi[0];
    __syncthreads();
}

__device__ int blk_isum(int v, int* redi, int tid) {
#pragma unroll
    for (int off = 16; off; off >>= 1) v += __shfl_down_sync(0xffffffffu, v, off);
    if ((tid & 31) == 0) redi[tid >> 5] = v;
    __syncthreads();
    if (tid < 32) {
        v = (tid < NWARP) ? redi[tid] : 0;
#pragma unroll
        for (int off = 16; off; off >>= 1) v += __shfl_down_sync(0xffffffffu, v, off);
        if (tid == 0) redi[0] = v;
    }
    __syncthreads();
    int r = redi[0];
    __syncthreads();
    return r;
}

// shared-hist top-tail cutoff: largest bin T with count(bins >= T) >= need
__device__ int cutoff_sh(const int* hist, int need, int* suf, int* selp, int* outp, int tid) {
    int part = 0;
    int b0 = tid * 8;
#pragma unroll
    for (int b = 0; b < 8; b++) part += hist[b0 + b];
    suf[tid] = part;
    __syncthreads();
    for (int off = 1; off < NT; off <<= 1) {
        int v = (tid + off < NT) ? suf[tid + off] : 0;
        __syncthreads();
        suf[tid] += v;
        __syncthreads();
    }
    if (suf[tid] >= need && (tid == NT - 1 || suf[tid + 1] < need)) *selp = tid;
    __syncthreads();
    if (tid == 0) {
        int c = *selp;
        int acc = (c < NT - 1) ? suf[c + 1] : 0;
        int T = c * 8;
        for (int b = c * 8 + 7; b >= c * 8; b--) {
            acc += hist[b];
            if (acc >= need) { T = b; break; }
        }
        *outp = T;
    }
    __syncthreads();
    int T = *outp;
    __syncthreads();
    return T;
}

// ---------------- K0: zero counters/flags ----------------
__global__ void k0_zero() {
    int i = threadIdx.x;
    if (i < B_) { g_nc[i] = 0; g_flag[i] = 0; }
}

// ---------------- K1: single streaming pass, shared-staged candidate append ----------------
__global__ __launch_bounds__(NT) void k1_stream(const float* __restrict__ logits) {
    __shared__ float scv[SHCAP];
    __shared__ int   sci[SHCAP];
    __shared__ int   scnt;
    __shared__ int   sbase;
    __shared__ float redf[NWARP];

    const int tid = threadIdx.x;
    const int r = blockIdx.x / QS, q = blockIdx.x % QS;
    const float4* q4 = (const float4*)(logits + (size_t)r * V_ + (size_t)q * VQ);
    const int base = q * VQ;
    if (tid == 0) scnt = 0;
    __syncthreads();

    float s0 = 0.f, s1 = 0.f, s2 = 0.f, s3 = 0.f;
    for (int i0 = tid; i0 < CQ; i0 += 2 * NT) {
        const int i1 = i0 + NT;
        const bool h2 = (i1 < CQ);
        float4 A = q4[i0];
        float4 Bv;
        if (h2) Bv = q4[i1];

        s0 += __expf(A.x); s1 += __expf(A.y); s2 += __expf(A.z); s3 += __expf(A.w);
        {
            int v0 = base + 4 * i0;
#pragma unroll
            for (int j = 0; j < 4; j++) {
                float lg = (&A.x)[j];
                if (lg >= TAU) {
                    int p = atomicAdd(&scnt, 1);
                    if (p < SHCAP) { scv[p] = lg; sci[p] = v0 + j; }
                }
            }
        }
        if (h2) {
            s0 += __expf(Bv.x); s1 += __expf(Bv.y); s2 += __expf(Bv.z); s3 += __expf(Bv.w);
            int v0 = base + 4 * i1;
#pragma unroll
            for (int j = 0; j < 4; j++) {
                float lg = (&Bv.x)[j];
                if (lg >= TAU) {
                    int p = atomicAdd(&scnt, 1);
                    if (p < SHCAP) { scv[p] = lg; sci[p] = v0 + j; }
                }
            }
        }
    }

    // exp-sum reduction
    float sv = (s0 + s1) + (s2 + s3);
#pragma unroll
    for (int off = 16; off; off >>= 1) sv += __shfl_down_sync(0xffffffffu, sv, off);
    if ((tid & 31) == 0) redf[tid >> 5] = sv;
    __syncthreads();
    if (tid < 32) {
        float v = (tid < NWARP) ? redf[tid] : 0.f;
#pragma unroll
        for (int off = 16; off; off >>= 1) v += __shfl_down_sync(0xffffffffu, v, off);
        if (tid == 0) g_expsum[r][q] = v;
    }

    // one global reservation per CTA, then coalesced flush
    __syncthreads();
    int n = scnt;
    if (n > SHCAP) { if (tid == 0) g_flag[r] = 1; n = SHCAP; }
    if (tid == 0) sbase = atomicAdd(&g_nc[r], n);
    __syncthreads();
    int bp = sbase;
    for (int i = tid; i < n; i += NT) {
        int off = bp + i;
        if (off < CCAP) { g_cval[r][off] = scv[i]; g_cidx[r][off] = sci[i]; }
    }
}

// ---------------- K2: per-row selection on candidates ----------------
struct M2 {
    int   suf[NT];
    float redf[NWARP];
    int   redi[NWARP];
    int   selp, outp, cnt, bad;
    float lse, thresh, t_thr, lp_samp;
    int   keepN, sampled;
};
#define C2_HKEY 0
#define C2_HAUX 8192
#define C2_CVAL 16384
#define C2_CIDX 32768
#define C2_XVAL 49152
#define C2_HIST 65536
#define C2_TMPV 81920
#define C2_TMPI 86016
#define C2_SSV  90112
#define C2_SSI  94208
#define C2_RSV  98304
#define C2_RSI  99328
#define C2_MISC 100352
#define K2_SMEM (C2_MISC + 2560)

__global__ __launch_bounds__(NT) void k2_select(
    const float* __restrict__ logits,
    const float* __restrict__ temperature, const float* __restrict__ top_p,
    const float* __restrict__ freqp, const float* __restrict__ presp,
    const float* __restrict__ repp, const int* __restrict__ topk,
    const int* __restrict__ ptoks, const int* __restrict__ otoks,
    float* __restrict__ out)
{
    extern __shared__ unsigned char sm[];
    int*   hkey = (int*)(sm + C2_HKEY);
    int*   haux = (int*)(sm + C2_HAUX);
    float* cval = (float*)(sm + C2_CVAL);
    int*   cidx = (int*)(sm + C2_CIDX);
    float* xval = (float*)(sm + C2_XVAL);
    int*   hist = (int*)(sm + C2_HIST);
    float* tmpv = (float*)(sm + C2_TMPV);
    int*   tmpi = (int*)(sm + C2_TMPI);
    float* ssv  = (float*)(sm + C2_SSV);
    int*   ssi  = (int*)(sm + C2_SSI);
    float* rsv  = (float*)(sm + C2_RSV);
    int*   rsi  = (int*)(sm + C2_RSI);
    M2*    ms   = (M2*)(sm + C2_MISC);

    const int tid = threadIdx.x, r = blockIdx.x;
    if (g_flag[r]) return;   // K1 overflow -> fallback row
    int k = topk[r];
    if (k < 1) k = 1; if (k > V_) k = V_;
    const int ncand = g_nc[r];
    if (ncand > CCAP || ncand < k + 640) { if (tid == 0) g_flag[r] = 1; return; }

    const float tr = temperature[r], tpv = top_p[r];
    const float fq = freqp[r], pp = presp[r], rp = repp[r];
    const float tsafe = (tr < EPS_T) ? 1.0f : tr;

    for (int i = tid; i < HB; i += NT) { hkey[i] = -1; haux[i] = 0; }
    for (int i = tid; i < NBIN; i += NT) hist[i] = 0;
    if (tid == 0) {
        ms->cnt = 0;
        float e = (g_expsum[r][0] + g_expsum[r][1]) + (g_expsum[r][2] + g_expsum[r][3]);
        ms->lse = logf(e);
    }
    __syncthreads();
    for (int t = tid; t < O_; t += NT) atomicAdd(&haux[hinsert(hkey, otoks[r * O_ + t])], 1);
    for (int t = tid; t < P_; t += NT) atomicOr(&haux[hinsert(hkey, ptoks[r * P_ + t])], 1 << 16);
    __syncthreads();

    // load candidates, compute adjusted x, histogram x
    for (int i = tid; i < ncand; i += NT) {
        float lg = g_cval[r][i]; int v = g_cidx[r][i];
        cval[i] = lg; cidx[i] = v;
        int slot = hfind(hkey, v);
        float x = (slot >= 0) ? adjv(lg, haux[slot], rp, fq, pp) : lg;
        xval[i] = x;
        atomicAdd(&hist[binOf(x)], 1);
    }
    __syncthreads();
    int Ts = cutoff_sh(hist, k, ms->suf, &ms->selp, &ms->outp, tid);

    // collect x survivors
    for (int i = tid; i < ncand; i += NT) {
        if (binOf(xval[i]) >= Ts) {
            int p = atomicAdd(&ms->cnt, 1);
            if (p < SSCAP) { tmpv[p] = xval[i]; tmpi[p] = cidx[i]; }
        }
    }
    __syncthreads();
    int ss = ms->cnt;
    if (ss > SSCAP) { if (tid == 0) g_flag[r] = 1; return; }
    // sort x survivors (val desc, idx asc)
    for (int i = tid; i < ss; i += NT) {
        float v = tmpv[i]; int id = tmpi[i]; int rk = 0;
        for (int j = 0; j < ss; j++) {
            float w = tmpv[j];
            rk += (w > v) || (w == v && tmpi[j] < id);
        }
        ssv[rk] = v; ssi[rk] = id;
    }
    __syncthreads();

    // raw hist (reuse)
    for (int i = tid; i < NBIN; i += NT) hist[i] = 0;
    if (tid == 0) ms->cnt = 0;
    __syncthreads();
    for (int i = tid; i < ncand; i += NT) atomicAdd(&hist[binOf(cval[i])], 1);
    __syncthreads();
    int Tr = cutoff_sh(hist, 20, ms->suf, &ms->selp, &ms->outp, tid);
    for (int i = tid; i < ncand; i += NT) {
        if (binOf(cval[i]) >= Tr) {
            int p = atomicAdd(&ms->cnt, 1);
            if (p < RRCAP) { tmpv[p] = cval[i]; tmpi[p] = cidx[i]; }
        }
    }
    __syncthreads();
    int rr = ms->cnt;
    if (rr > RRCAP) { if (tid == 0) g_flag[r] = 1; return; }
    for (int i = tid; i < rr; i += NT) {
        float v = tmpv[i]; int id = tmpi[i]; int rk = 0;
        for (int j = 0; j < rr; j++) {
            float w = tmpv[j];
            rk += (w > v) || (w == v && tmpi[j] < id);
        }
        rsv[rk] = v; rsi[rk] = id;
    }
    __syncthreads();

    // top-k / top-p threshold
    if (tid == 0) {
        int kk = (k <= ss) ? k : ss;
        float kth_s = ssv[kk - 1] / tsafe;
        int keepN = kk;
        while (keepN < ss && (ssv[keepN] / tsafe) >= kth_s) keepN++;
        float s0 = ssv[0] / tsafe;
        float S = 0.0f;
        for (int i = 0; i < keepN; i++) S += expf(ssv[i] / tsafe - s0);
        float cum = 0.0f; int j = 0;
        for (int i = 0; i < keepN; i++) {
            float p = expf(ssv[i] / tsafe - s0) / S;
            if (cum < tpv) j++;
            cum += p;
        }
        if (cum < tpv) j += (V_ - keepN);   // zero-prob tail all keeps
        int nkeep = (j < 1) ? 1 : j;
        float pth = (nkeep <= keepN) ? (ssv[nkeep - 1] / tsafe) : NEG_INF;
        ms->thresh = fmaxf(kth_s, pth);
        ms->keepN = keepN;
    }
    __syncthreads();
    const float thresh = ms->thresh;
    const int keepN = ms->keepN;
    const float lse = ms->lse;

    // gumbel argmax over kept candidates
    float bv = NEG_INF; int bidx = 0x7fffffff;
    for (int i = tid; i < keepN; i += NT) {
        float s = ssv[i] / tsafe;
        if (s >= thresh) {
            float g = gumbel_at((unsigned)(r * V_) + (unsigned)ssi[i]);
            float val = s + g;
            if (val > bv || (val == bv && ssi[i] < bidx)) { bv = val; bidx = ssi[i]; }
        }
    }
    float rv; int ri;
    blk_argmax(bv, bidx, ms->redf, ms->redi, tid, &rv, &ri);
    if (tid == 0) {
        int sampled = (tr < EPS_T) ? ssi[0] : ri;   // greedy = first-index argmax of x
        ms->sampled = sampled;
        float lgs = logits[(size_t)r * V_ + sampled];
        float c = lgs - lse;
        ms->lp_samp = c;
        unsigned lo = 0u, hi = f2ord(lgs);
        while (lo < hi) {
            unsigned mid = lo + ((hi - lo) >> 1);
            float y = ord2f(mid);
            if ((y - lse) >= c) hi = mid; else lo = mid + 1;
        }
        float t = ord2f(hi);
        ms->t_thr = t;
        ms->bad = (t < TAU) ? 1 : 0;
        if (ms->bad) g_flag[r] = 1;
    }
    __syncthreads();
    if (ms->bad) return;
    const float t_thr = ms->t_thr;

    // rank: count candidates with lg >= t_thr (complete since t_thr >= TAU)
    int cnt = 0;
    for (int i = tid; i < ncand; i += NT) cnt += (cval[i] >= t_thr) ? 1 : 0;
    int total = blk_isum(cnt, ms->redi, tid);

    // outputs
    if (tid < 20) {
        out[IDX_OFF + r * 21 + tid] = (float)rsi[tid];
        out[LP_OFF  + r * 21 + tid] = rsv[tid] - lse;
    }
    if (tid == 0) {
        out[r] = (float)ms->sampled;
        out[IDX_OFF + r * 21 + 20] = (float)ms->sampled;
        out[LP_OFF  + r * 21 + 20] = ms->lp_samp;
        out[RK_OFF + r] = (float)total;
    }
}

// ---------------- K3: exact fallback, runs only when flagged ----------------
struct FbMisc {
    int   suf[NT];
    float redf[NWARP];
    float redf2[NWARP];
    int   redi[NWARP];
    float m, logS, thresh, lp_samp, t_thr;
    int   Ts, Tr, nsCnt, nrCnt, selp, outp, keepN, sampled, rank_ok;
};
#define FB_HKEY  0
#define FB_HAUX  8192
#define FB_HISTR 16384
#define FB_HISTS 32768
#define FB_SVAL  16384
#define FB_SIDX  24576
#define FB_RVAL  32768
#define FB_RIDX  36864
#define FB_SSV   0
#define FB_SSI   8192
#define FB_RSV   40960
#define FB_RSI   45056
#define FB_MISC  49152
#define FB_SMEM  (FB_MISC + 2816)

__global__ __launch_bounds__(NT) void k3_fallback(
    const float* __restrict__ logits,
    const float* __restrict__ temperature, const float* __restrict__ top_p,
    const float* __restrict__ freqp, const float* __restrict__ presp,
    const float* __restrict__ repp, const int* __restrict__ topk,
    const int* __restrict__ ptoks, const int* __restrict__ otoks,
    float* __restrict__ out)
{
    const int r = blockIdx.x;
    if (g_flag[r] == 0) return;

    extern __shared__ unsigned char sm[];
    int*    hkey  = (int*)(sm + FB_HKEY);
    int*    haux  = (int*)(sm + FB_HAUX);
    int*    histR = (int*)(sm + FB_HISTR);
    int*    histS = (int*)(sm + FB_HISTS);
    FbMisc* ms    = (FbMisc*)(sm + FB_MISC);

    const int tid = threadIdx.x;
    const float* row = logits + (size_t)r * V_;
    const float4* row4 = (const float4*)row;

    const float tr  = temperature[r];
    const float tpv = top_p[r];
    const float fq  = freqp[r];
    const float pp  = presp[r];
    const float rp  = repp[r];
    int k = topk[r];
    if (k < 1) k = 1; if (k > V_) k = V_;
    const float tsafe = (tr < EPS_T) ? 1.0f : tr;

    for (int i = tid; i < NBIN; i += NT) histR[i] = 0;
    for (int i = tid; i < HB; i += NT) { hkey[i] = -1; haux[i] = 0; }
    if (tid == 0) { ms->nsCnt = 0; ms->nrCnt = 0; }
    __syncthreads();

    for (int t = tid; t < O_; t += NT) atomicAdd(&haux[hinsert(hkey, otoks[r * O_ + t])], 1);
    for (int t = tid; t < P_; t += NT) atomicOr(&haux[hinsert(hkey, ptoks[r * P_ + t])], 1 << 16);
    __syncthreads();

    float ml0 = NEG_INF, ml1 = NEG_INF, ml2 = NEG_INF, ml3 = NEG_INF;
    float sl0 = 0.f, sl1 = 0.f, sl2 = 0.f, sl3 = 0.f;
    for (int i = tid; i < V_ / 4; i += NT) {
        float4 L = row4[i];
        if (L.x > ml0) { sl0 = sl0 * __expf(ml0 - L.x) + 1.0f; ml0 = L.x; } else sl0 += __expf(L.x - ml0);
        if (L.y > ml1) { sl1 = sl1 * __expf(ml1 - L.y) + 1.0f; ml1 = L.y; } else sl1 += __expf(L.y - ml1);
        if (L.z > ml2) { sl2 = sl2 * __expf(ml2 - L.z) + 1.0f; ml2 = L.z; } else sl2 += __expf(L.z - ml2);
        if (L.w > ml3) { sl3 = sl3 * __expf(ml3 - L.w) + 1.0f; ml3 = L.w; } else sl3 += __expf(L.w - ml3);
        atomicAdd(&histR[binOf(L.x)], 1);
        atomicAdd(&histR[binOf(L.y)], 1);
        atomicAdd(&histR[binOf(L.z)], 1);
        atomicAdd(&histR[binOf(L.w)], 1);
    }
    float mloc = fmaxf(fmaxf(ml0, ml1), fmaxf(ml2, ml3));
    float sloc = 0.0f;
    if (ml0 > NEG_INF) sloc += sl0 * __expf(ml0 - mloc);
    if (ml1 > NEG_INF) sloc += sl1 * __expf(ml1 - mloc);
    if (ml2 > NEG_INF) sloc += sl2 * __expf(ml2 - mloc);
    if (ml3 > NEG_INF) sloc += sl3 * __expf(ml3 - mloc);
    {
#pragma unroll
        for (int off = 16; off; off >>= 1) {
            float m2 = __shfl_down_sync(0xffffffffu, mloc, off);
            float s2 = __shfl_down_sync(0xffffffffu, sloc, off);
            float nm = fmaxf(mloc, m2);
            sloc = sloc * __expf(mloc - nm) + s2 * __expf(m2 - nm);
            mloc = nm;
        }
        if ((tid & 31) == 0) { ms->redf[tid >> 5] = mloc; ms->redf2[tid >> 5] = sloc; }
        __syncthreads();
        if (tid < 32) {
            float mm = (tid < NWARP) ? ms->redf[tid] : NEG_INF;
            float ssx = (tid < NWARP) ? ms->redf2[tid] : 0.0f;
#pragma unroll
            for (int off = 16; off; off >>= 1) {
                float m2 = __shfl_down_sync(0xffffffffu, mm, off);
                float s2 = __shfl_down_sync(0xffffffffu, ssx, off);
                float nm = fmaxf(mm, m2);
                ssx = ssx * __expf(mm - nm) + s2 * __expf(m2 - nm);
                mm = nm;
            }
            if (tid == 0) { ms->m = mm; ms->logS = logf(ssx); }
        }
        __syncthreads();
    }
    const float m = ms->m, logS = ms->logS;

    for (int i = tid; i < NBIN; i += NT) histS[i] = histR[i];
    __syncthreads();
    for (int s = tid; s < HB; s += NT) {
        int v = hkey[s];
        if (v >= 0) {
            float lg = row[v];
            float x = adjv(lg, haux[s], rp, fq, pp);
            int b1 = binOf(lg), b2 = binOf(x);
            if (b1 != b2) { atomicSub(&histS[b1], 1); atomicAdd(&histS[b2], 1); }
        }
    }
    __syncthreads();

    int Ts = cutoff_sh(histS, k, ms->suf, &ms->selp, &ms->outp, tid);
    int Tr = cutoff_sh(histR, 20, ms->suf, &ms->selp, &ms->outp, tid);
    if (tid == 0) { ms->Ts = Ts; ms->Tr = Tr; }
    const int Tmin = (Ts < Tr) ? Ts : Tr;
    __syncthreads();

    float* s_val = (float*)(sm + FB_SVAL);
    int*   s_idx = (int*)(sm + FB_SIDX);
    float* r_val = (float*)(sm + FB_RVAL);
    int*   r_idx = (int*)(sm + FB_RIDX);

    for (int i = tid; i < V_ / 4; i += NT) {
        float4 L = row4[i];
        int v0 = 4 * i;
#pragma unroll
        for (int j = 0; j < 4; j++) {
            float lg = (&L.x)[j];
            int b = binOf(lg);
            if (b >= Tmin) {
                int v = v0 + j;
                if (b >= Tr) {
                    int p = atomicAdd(&ms->nrCnt, 1);
                    if (p < FB_RCAP) { r_val[p] = lg; r_idx[p] = v; }
                }
                if (b >= Ts) {
                    float x = lg;
                    int slot = hfind(hkey, v);
                    if (slot >= 0) x = adjv(lg, haux[slot], rp, fq, pp);
                    if (binOf(x) >= Ts) {
                        int ps = atomicAdd(&ms->nsCnt, 1);
                        if (ps < FB_SCAP) { s_val[ps] = x; s_idx[ps] = v; }
                    }
                }
            }
        }
    }
    __syncthreads();
    int ns = ms->nsCnt; if (ns > FB_SCAP) ns = FB_SCAP;
    int nr = ms->nrCnt; if (nr > FB_RCAP) nr = FB_RCAP;
    int nrFull = ms->nrCnt;
    __syncthreads();

    float* ssv2 = (float*)(sm + FB_SSV);
    int*   ssi2 = (int*)(sm + FB_SSI);
    float* rsv2 = (float*)(sm + FB_RSV);
    int*   rsi2 = (int*)(sm + FB_RSI);

    for (int i = tid; i < ns; i += NT) {
        float v = s_val[i]; int id = s_idx[i]; int rk = 0;
        for (int j = 0; j < ns; j++) {
            float w = s_val[j];
            rk += (w > v) || (w == v && s_idx[j] < id);
        }
        ssv2[rk] = v; ssi2[rk] = id;
    }
    for (int i = tid; i < nr; i += NT) {
        float v = r_val[i]; int id = r_idx[i]; int rk = 0;
        for (int j = 0; j < nr; j++) {
            float w = r_val[j];
            rk += (w > v) || (w == v && r_idx[j] < id);
        }
        rsv2[rk] = v; rsi2[rk] = id;
    }
    __syncthreads();

    if (tid == 0) {
        int kk = (k <= ns) ? k : ns;
        float kth_s = ssv2[kk - 1] / tsafe;
        int keepN = kk;
        while (keepN < ns && (ssv2[keepN] / tsafe) >= kth_s) keepN++;
        float s0 = ssv2[0] / tsafe;
        float S = 0.0f;
        for (int i = 0; i < keepN; i++) S += expf(ssv2[i] / tsafe - s0);
        float cum = 0.0f; int j = 0;
        for (int i = 0; i < keepN; i++) {
            float p = expf(ssv2[i] / tsafe - s0) / S;
            if (cum < tpv) j++;
            cum += p;
        }
        if (cum < tpv) j += (V_ - keepN);
        int nkeep = (j < 1) ? 1 : j;
        float pth = (nkeep <= keepN) ? (ssv2[nkeep - 1] / tsafe) : NEG_INF;
        ms->thresh = fmaxf(kth_s, pth);
        ms->keepN = keepN;
    }
    __syncthreads();
    const float thresh = ms->thresh;
    const int keepN = ms->keepN;

    {
        float bv = NEG_INF; int bidx = 0x7fffffff;
        for (int i = tid; i < keepN; i += NT) {
            float s = ssv2[i] / tsafe;
            if (s >= thresh) {
                float g = gumbel_at((unsigned)(r * V_) + (unsigned)ssi2[i]);
                float val = s + g;
                if (val > bv || (val == bv && ssi2[i] < bidx)) { bv = val; bidx = ssi2[i]; }
            }
        }
        float rv; int ri;
        blk_argmax(bv, bidx, ms->redf, ms->redi, tid, &rv, &ri);
        if (tid == 0) {
            int sampled = (tr < EPS_T) ? ssi2[0] : ri;
            ms->sampled = sampled;
            float lgs = row[sampled];
            float c = (lgs - m) - logS;
            ms->lp_samp = c;
            unsigned lo = 0u, hi = f2ord(lgs);
            while (lo < hi) {
                unsigned mid = lo + ((hi - lo) >> 1);
                float y = ord2f(mid);
                if (((y - m) - logS) >= c) hi = mid; else lo = mid + 1;
            }
            float t = ord2f(hi);
            ms->t_thr = t;
            ms->rank_ok = (binOf(t) >= ms->Tr) && (nrFull <= FB_RCAP);
        }
        __syncthreads();
    }
    const int sampled = ms->sampled;
    const float lp_samp = ms->lp_samp;
    const float t_thr = ms->t_thr;
    const int rank_ok = ms->rank_ok;

    if (tid < 20) {
        out[IDX_OFF + r * 21 + tid] = (float)rsi2[tid];
        out[LP_OFF  + r * 21 + tid] = (rsv2[tid] - m) - logS;
    }
    if (tid == 0) {
        out[r] = (float)sampled;
        out[IDX_OFF + r * 21 + 20] = (float)sampled;
        out[LP_OFF  + r * 21 + 20] = lp_samp;
    }

    int cnt = 0;
    if (rank_ok) {
        for (int i = tid; i < nr; i += NT) cnt += (rsv2[i] >= t_thr) ? 1 : 0;
    } else {
        for (int i = tid; i < V_ / 4; i += NT) {
            float4 L = row4[i];
            cnt += (L.x >= t_thr) + (L.y >= t_thr) + (L.z >= t_thr) + (L.w >= t_thr);
        }
    }
    int total = blk_isum(cnt, ms->redi, tid);
    if (tid == 0) out[RK_OFF + r] = (float)total;
}

// ---------------- launch ----------------
extern "C" void kernel_launch(void* const* d_in, const int* in_sizes, int n_in,
                              void* d_out, int out_size) {
    const float* logits = (const float*)d_in[0];
    const float* temperature = (const float*)d_in[1];
    const float* topp = (const float*)d_in[2];
    const float* freqp = (const float*)d_in[3];
    const float* presp = (const float*)d_in[4];
    const float* repp = (const float*)d_in[5];
    const int* topk = (const int*)d_in[6];
    const int* ptoks = (const int*)d_in[7];
    const int* otoks = (const int*)d_in[8];
    float* out = (float*)d_out;

    cudaFuncSetAttribute(k2_select, cudaFuncAttributeMaxDynamicSharedMemorySize, K2_SMEM);
    cudaFuncSetAttribute(k3_fallback, cudaFuncAttributeMaxDynamicSharedMemorySize, FB_SMEM);

    k0_zero<<<1, NT>>>();
    k1_stream<<<B_ * QS, NT>>>(logits);
    k2_select<<<B_, NT, K2_SMEM>>>(logits, temperature, topp, freqp, presp, repp,
                                   topk, ptoks, otoks, out);
    k3_fallback<<<B_, NT, FB_SMEM>>>(logits, temperature, topp, freqp, presp, repp,
                                     topk, ptoks, otoks, out);
}